// round 16
// baseline (speedup 1.0000x reference)
#include <cuda_runtime.h>
#include <cuda_fp16.h>
#include <math.h>
#include <stdint.h>

#define NN 50000
#define EE 800000
#define ET 850000   // EE + NN self loops
#define GG 512
#define SCB 25      // scan blocks (2048 elems each)

// ---------------- static scratch (no allocations allowed) ----------------
__device__ __align__(128) __half g_y1[(size_t)NN * 512];  // [xl1 | xr1] fp16
__device__ __align__(128) __half g_h1[(size_t)NN * 256];  // post-ELU layer1 output fp16
__device__ __align__(128) __half g_y2[(size_t)NN * 256];  // [xl2 | xr2] fp16
__device__ __align__(128) __half g_B1[512 * 128];  // layer1 B^T fp16 [n][k]
__device__ __align__(128) __half g_B2[256 * 256];  // layer2 B^T fp16 [n][k]
__device__ int    g_deg[NN];
__device__ int    g_off[NN + 1];
__device__ int    g_cur[NN];
__device__ int    g_csrc[ET];
__device__ int    g_blksum[32];
__device__ float  g_bnsumF[256];
__device__ float  g_bnsqF[256];
__device__ float  g_acc[GG * 2];   // per-graph projected sums
__device__ float  g_cnt[GG];
__device__ unsigned g_done;

// ---------------- PTX helpers (baseline sm_80/sm_90 features only) ----------------
__device__ __forceinline__ uint32_t smem_u32(const void* p) {
    uint32_t r;
    asm("{ .reg .u64 t; cvta.to.shared.u64 t, %1; cvt.u32.u64 %0, t; }" : "=r"(r) : "l"(p));
    return r;
}
#define CP_ASYNC16(dst, src) \
    asm volatile("cp.async.cg.shared.global [%0], [%1], 16;" :: "r"(dst), "l"(src) : "memory")
#define CP_COMMIT() asm volatile("cp.async.commit_group;" ::: "memory")
#define CP_WAIT(n)  asm volatile("cp.async.wait_group %0;" :: "n"(n) : "memory")
#define LDM_X4(r0, r1, r2, r3, addr) \
    asm volatile("ldmatrix.sync.aligned.m8n8.x4.shared.b16 {%0,%1,%2,%3}, [%4];" \
        : "=r"(r0), "=r"(r1), "=r"(r2), "=r"(r3) : "r"(addr))
#define MMA_F16(cc, a, b0v, b1v) \
    asm volatile("mma.sync.aligned.m16n8k16.row.col.f32.f16.f16.f32 " \
        "{%0,%1,%2,%3}, {%4,%5,%6,%7}, {%8,%9}, {%0,%1,%2,%3};" \
        : "+f"((cc)[0]), "+f"((cc)[1]), "+f"((cc)[2]), "+f"((cc)[3]) \
        : "r"((a)[0]), "r"((a)[1]), "r"((a)[2]), "r"((a)[3]), "r"(b0v), "r"(b1v))

__device__ __forceinline__ uint32_t pkh2(float a, float b) {
    __half2 t = __floats2half2_rn(a, b);
    return *reinterpret_cast<uint32_t*>(&t);
}

// ---------------- init (on CSR side stream; zeroes deg for hist) ----------------
__global__ void k_initMain() {
    int i = blockIdx.x * blockDim.x + threadIdx.x;  // 65536 threads
    if (i < GG * 2) g_acc[i] = 0.f;
    if (i < GG) g_cnt[i] = 0.f;
    if (i < 256) { g_bnsumF[i] = 0.f; g_bnsqF[i] = 0.f; }
    if (i < NN) g_deg[i] = 0;
    if (i == 0) g_done = 0u;
}

// ---------------- convert & transpose weights (fp16) ----------------
__global__ void k_cvtB1(const float* __restrict__ Wl1, const float* __restrict__ Wr1) {
    int i = blockIdx.x * blockDim.x + threadIdx.x;  // 65536 threads
    if (i < 512 * 128) {
        int n = i >> 7, k = i & 127;
        float w = (n < 256) ? Wl1[k * 256 + n] : Wr1[k * 256 + (n - 256)];
        g_B1[i] = __float2half(w);
    }
}

__global__ void k_cvtB2(const float* __restrict__ Wl2, const float* __restrict__ Wr2) {
    int j = blockIdx.x * blockDim.x + threadIdx.x;  // 65536 threads
    if (j < 256 * 256) {
        int n = j >> 8, k = j & 255;
        float w = (n < 128) ? Wl2[k * 128 + n] : Wr2[k * 128 + (n - 128)];
        g_B2[j] = __float2half(w);
    }
}

// ---------------- CSR build ----------------
__global__ void k_hist(const int* __restrict__ ei) {
    int i = blockIdx.x * blockDim.x + threadIdx.x;
    if (i >= ET) return;
    int dst = (i < EE) ? ei[EE + i] : (i - EE);
    atomicAdd(&g_deg[dst], 1);
}

// hierarchical scan: A) block sums, C) per-block scan of sums + full scan + write
__global__ void k_scanA() {  // grid SCB, block 1024
    __shared__ int ws[32];
    const int b = blockIdx.x, t = threadIdx.x;
    const int i = b * 2048 + 2 * t;
    int v0 = 0, v1 = 0;
    if (i + 1 < NN) { int2 p = *(const int2*)&g_deg[i]; v0 = p.x; v1 = p.y; }
    else if (i < NN) v0 = g_deg[i];
    int s = v0 + v1;
#pragma unroll
    for (int o = 16; o; o >>= 1) s += __shfl_xor_sync(0xffffffffu, s, o);
    if ((t & 31) == 0) ws[t >> 5] = s;
    __syncthreads();
    if (t < 32) {
        int x = ws[t];
#pragma unroll
        for (int o = 16; o; o >>= 1) x += __shfl_xor_sync(0xffffffffu, x, o);
        if (t == 0) g_blksum[b] = x;
    }
}

__global__ void k_scanC() {  // grid SCB, block 1024: scans blksums itself, then full scan
    __shared__ int ws[32];
    __shared__ int sOff, sTotal;
    const int b = blockIdx.x, t = threadIdx.x;
    const int lane = t & 31, w = t >> 5;

    if (t < 32) {  // warp 0: exclusive-scan the 25 block sums
        int v = (t < SCB) ? g_blksum[t] : 0;
        int x = v;
#pragma unroll
        for (int o = 1; o < 32; o <<= 1) {
            int u = __shfl_up_sync(0xffffffffu, x, o);
            if (t >= o) x += u;
        }
        if (t == b) sOff = x - v;
        if (t == SCB - 1) sTotal = x;
    }

    const int i = b * 2048 + 2 * t;
    int v0 = 0, v1 = 0;
    if (i + 1 < NN) { int2 p = *(const int2*)&g_deg[i]; v0 = p.x; v1 = p.y; }
    else if (i < NN) v0 = g_deg[i];
    int s = v0 + v1;
    int x = s;
#pragma unroll
    for (int o = 1; o < 32; o <<= 1) {
        int u = __shfl_up_sync(0xffffffffu, x, o);
        if (lane >= o) x += u;
    }
    if (lane == 31) ws[w] = x;
    __syncthreads();
    if (w == 0) {
        int y = ws[lane];
#pragma unroll
        for (int o = 1; o < 32; o <<= 1) {
            int u = __shfl_up_sync(0xffffffffu, y, o);
            if (lane >= o) y += u;
        }
        ws[lane] = y;
    }
    __syncthreads();
    int excl = x - s + (w > 0 ? ws[w - 1] : 0) + sOff;
    if (i < NN) { g_off[i] = excl; g_cur[i] = excl; }
    if (i + 1 < NN) { g_off[i + 1] = excl + v0; g_cur[i + 1] = excl + v0; }
    if (b == SCB - 1 && t == 1023) g_off[NN] = sTotal;
}

__global__ void k_fill(const int* __restrict__ ei) {
    int i = blockIdx.x * blockDim.x + threadIdx.x;
    if (i >= ET) return;
    int src = (i < EE) ? ei[i] : (i - EE);
    int dst = (i < EE) ? ei[EE + i] : (i - EE);
    int p = atomicAdd(&g_cur[dst], 1);
    g_csrc[p] = src;
}

// ---------------- single-pass fp16 mma.sync GEMM ----------------
// NORM: compute BN scale/shift per block from raw sums (folds bnfin).
template <int K, bool NORM, typename TA>
__global__ void __launch_bounds__(256, 2) k_mma(
    const TA* __restrict__ A,
    const __half* __restrict__ B,
    __half* __restrict__ C, int ldc, int M,
    const float* __restrict__ gamma, const float* __restrict__ beta) {
    extern __shared__ __align__(128) char smem[];
    constexpr int NC = K / 32;
    const int tid = threadIdx.x, lane = tid & 31, wid = tid >> 5;
    const int row0 = blockIdx.y * 128, n0 = blockIdx.x * 128;
    const int wm = (wid & 3) * 32, wn = (wid >> 2) * 64;
    const uint32_t sb = smem_u32(smem);
    float* sScale = (float*)(smem + 40960);
    float* sShift = (float*)(smem + 40960 + 1024);

    if (NORM) {
        if (tid < K) {
            float mu = g_bnsumF[tid] * (1.f / (float)NN);
            float var = g_bnsqF[tid] * (1.f / (float)NN) - mu * mu;
            float sc = gamma[tid] * rsqrtf(var + 1e-5f);
            sScale[tid] = sc;
            sShift[tid] = beta[tid] - mu * sc;
        }
        __syncthreads();
    }

    float c[2][8][4];
#pragma unroll
    for (int mf = 0; mf < 2; mf++)
#pragma unroll
        for (int nf = 0; nf < 8; nf++)
#pragma unroll
            for (int q = 0; q < 4; q++) c[mf][nf][q] = 0.f;

    const int ar = tid >> 1;             // A row within tile
    const int ac = (tid & 1) * 16;       // A col-seg within chunk
    const int agr = min(row0 + ar, M - 1);

    auto ldgA = [&](int ch, float* f) {
        const TA* ap = A + (size_t)agr * K + ch * 32 + ac;
        if (sizeof(TA) == 4) {
            const float* fp = (const float*)ap;
#pragma unroll
            for (int q = 0; q < 4; q++) {
                float4 v = *(const float4*)(fp + q * 4);
                f[q * 4 + 0] = v.x; f[q * 4 + 1] = v.y;
                f[q * 4 + 2] = v.z; f[q * 4 + 3] = v.w;
            }
        } else {
            const __half2* hp = (const __half2*)ap;
#pragma unroll
            for (int q = 0; q < 8; q++) {
                float2 v = __half22float2(hp[q]);
                f[q * 2 + 0] = v.x; f[q * 2 + 1] = v.y;
            }
        }
    };
    auto stsA = [&](int ch, float* f) {
        const uint32_t base = (uint32_t)(ch & 1) * 20480u;
        if (NORM) {
            const int c0 = ch * 32 + ac;
#pragma unroll
            for (int i = 0; i < 16; i++) f[i] = fmaf(f[i], sScale[c0 + i], sShift[c0 + i]);
        }
        uint4 H0 = make_uint4(pkh2(f[0], f[1]), pkh2(f[2], f[3]), pkh2(f[4], f[5]), pkh2(f[6], f[7]));
        uint4 H1 = make_uint4(pkh2(f[8], f[9]), pkh2(f[10], f[11]), pkh2(f[12], f[13]), pkh2(f[14], f[15]));
        const uint32_t off = base + (uint32_t)ar * 80u + (uint32_t)ac * 2u;
        *(uint4*)(smem + off) = H0;
        *(uint4*)(smem + off + 16) = H1;
    };
    auto issueB = [&](int ch) {
        const int k0 = ch * 32;
        const uint32_t base = sb + (uint32_t)(ch & 1) * 20480u + 10240u;
#pragma unroll
        for (int j = 0; j < 2; j++) {
            int seg = tid + 256 * j;
            int r = seg >> 2, s = seg & 3;
            const void* src = B + (size_t)(n0 + r) * K + k0 + s * 8;
            uint32_t dst = base + (uint32_t)r * 80u + (uint32_t)s * 16u;
            CP_ASYNC16(dst, src);
        }
    };

    // prologue
    float areg[16];
    ldgA(0, areg);
    stsA(0, areg);
    issueB(0);
    CP_COMMIT();
    if (NC > 1) {
        issueB(1);
        CP_COMMIT();
        ldgA(1, areg);
    }

    // ldmatrix per-lane address pieces
    const int grp = lane >> 3, r8 = lane & 7;
    const uint32_t a_row = (uint32_t)(((grp & 1) ? 8 : 0) + r8);
    const uint32_t a_k16 = (grp & 2) ? 16u : 0u;
    const uint32_t b_row = (uint32_t)(((grp & 2) ? 8 : 0) + r8);
    const uint32_t b_k16 = (grp & 1) ? 16u : 0u;

    for (int ch = 0; ch < NC; ch++) {
        if (ch + 1 < NC) { CP_WAIT(1); } else { CP_WAIT(0); }
        __syncthreads();
        const uint32_t sA = sb + (uint32_t)(ch & 1) * 20480u;
#pragma unroll
        for (int ks = 0; ks < 2; ks++) {
            const uint32_t ko = (uint32_t)ks * 32u;
            uint32_t ah[2][4], bh[4][4];
#pragma unroll
            for (int mf = 0; mf < 2; mf++) {
                uint32_t addr = sA + ((uint32_t)(wm + mf * 16) + a_row) * 80u + ko + a_k16;
                LDM_X4(ah[mf][0], ah[mf][1], ah[mf][2], ah[mf][3], addr);
            }
#pragma unroll
            for (int pf = 0; pf < 4; pf++) {
                uint32_t addr = sA + 10240u + ((uint32_t)(wn + pf * 16) + b_row) * 80u + ko + b_k16;
                LDM_X4(bh[pf][0], bh[pf][1], bh[pf][2], bh[pf][3], addr);
            }
#pragma unroll
            for (int mf = 0; mf < 2; mf++)
#pragma unroll
                for (int nf = 0; nf < 8; nf++) {
                    const int pf = nf >> 1, h = (nf & 1) * 2;
                    MMA_F16(c[mf][nf], ah[mf], bh[pf][h], bh[pf][h + 1]);
                }
        }
        if (ch + 1 < NC) {
            stsA(ch + 1, areg);               // other buffer: safe pre-sync
            if (ch + 2 < NC) ldgA(ch + 2, areg);
        }
        __syncthreads();
        if (ch + 2 < NC) {
            issueB(ch + 2);                    // reuses buffer (ch&1): safe post-sync
            CP_COMMIT();
        }
    }

    // epilogue (fp16 stores)
    const int g = lane >> 2, tg = lane & 3;
#pragma unroll
    for (int mf = 0; mf < 2; mf++) {
        int row = row0 + wm + mf * 16 + g;
#pragma unroll
        for (int nf = 0; nf < 8; nf++) {
            int col = n0 + wn + nf * 8 + 2 * tg;
            if (row < M)
                *(__half2*)(C + (size_t)row * ldc + col) = __floats2half2_rn(c[mf][nf][0], c[mf][nf][1]);
            if (row + 8 < M)
                *(__half2*)(C + (size_t)(row + 8) * ldc + col) = __floats2half2_rn(c[mf][nf][2], c[mf][nf][3]);
        }
    }
}

// ---------------- GATv2 aggregation: warp per dst node, branch-free online softmax ----
// Processes 2 edges per iteration (shared corr rescale, overlapped d-reductions).
// FINAL: fuse mean-pool projection (@Wlin) -> 2 atomics per node; last block writes out.
template <int HEADS, bool FINAL>
__global__ void k_agg(const __half* __restrict__ y,     // [NN, 2*CH] = [xl | xr] fp16
                      const float* __restrict__ att,    // [CH]
                      const float* __restrict__ bias,   // [CH]
                      __half* __restrict__ hout,        // [NN, CH] fp16 (if !FINAL)
                      const int* __restrict__ batch,
                      const float* __restrict__ Wlin,   // [CH, 2] (if FINAL)
                      const float* __restrict__ blin,   // [2]     (if FINAL)
                      float* __restrict__ out) {        // [GG, 2] (if FINAL)
    constexpr int CH = HEADS * 128;
    constexpr int NCH = CH / 32;       // channels per lane (8 or 4)
    constexpr int NH2 = NCH / 2;       // half2 per lane (4 or 2)
    constexpr int LPH = 32 / HEADS;    // lanes per head
    __shared__ int sLast;
    const int lane = threadIdx.x & 31;
    const int t = (blockIdx.x * blockDim.x + threadIdx.x) >> 5;
    const bool active = t < NN;
    const int c0 = NCH * lane;         // this lane's first channel

    float2 xr[NH2], attv[NH2], acc[NH2];
#pragma unroll
    for (int k = 0; k < NH2; k++) {
        xr[k] = make_float2(0.f, 0.f);
        attv[k] = make_float2(att[c0 + 2 * k], att[c0 + 2 * k + 1]);
        acc[k] = make_float2(0.f, 0.f);
    }
    if (active) {
        const __half* yt = y + (size_t)t * (2 * CH) + CH + c0;  // xr[t] block
#pragma unroll
        for (int k = 0; k < NH2; k++)
            xr[k] = __half22float2(*(const __half2*)(yt + 2 * k));
    }
    float emax = -1e30f, den = 0.f;

    const int s0 = active ? g_off[t] : 0;
    const int s1 = active ? g_off[t + 1] : 0;
    int j = s0;
    for (; j + 2 <= s1; j += 2) {
        int sA = g_csrc[j], sB = g_csrc[j + 1];
        const __half* yA = y + (size_t)sA * (2 * CH) + c0;
        const __half* yB = y + (size_t)sB * (2 * CH) + c0;
        uint32_t vA[NH2], vB[NH2];
        if (NH2 == 4) {
            uint4 uA = *(const uint4*)yA;
            uint4 uB = *(const uint4*)yB;
            vA[0] = uA.x; vA[1] = uA.y; vA[2] = uA.z; vA[3] = uA.w;
            vB[0] = uB.x; vB[1] = uB.y; vB[2] = uB.z; vB[3] = uB.w;
        } else {
            uint2 uA = *(const uint2*)yA;
            uint2 uB = *(const uint2*)yB;
            vA[0] = uA.x; vA[1] = uA.y;
            vB[0] = uB.x; vB[1] = uB.y;
        }
        float2 xvA[NH2], xvB[NH2];
        float d0 = 0.f, d1 = 0.f;
#pragma unroll
        for (int k = 0; k < NH2; k++) {
            float2 a = __half22float2(*reinterpret_cast<__half2*>(&vA[k]));
            float2 b = __half22float2(*reinterpret_cast<__half2*>(&vB[k]));
            xvA[k] = a; xvB[k] = b;
            float ax = a.x + xr[k].x, ay = a.y + xr[k].y;
            float bx = b.x + xr[k].x, by = b.y + xr[k].y;
            ax = fmaxf(ax, 0.2f * ax); ay = fmaxf(ay, 0.2f * ay);
            bx = fmaxf(bx, 0.2f * bx); by = fmaxf(by, 0.2f * by);
            d0 = fmaf(ax, attv[k].x, d0); d0 = fmaf(ay, attv[k].y, d0);
            d1 = fmaf(bx, attv[k].x, d1); d1 = fmaf(by, attv[k].y, d1);
        }
#pragma unroll
        for (int o = LPH >> 1; o; o >>= 1) {
            d0 += __shfl_xor_sync(0xffffffffu, d0, o);
            d1 += __shfl_xor_sync(0xffffffffu, d1, o);
        }
        float nm = fmaxf(emax, fmaxf(d0, d1));
        float corr = __expf(emax - nm);
        float e0 = __expf(d0 - nm);
        float e1 = __expf(d1 - nm);
        emax = nm;
        den = fmaf(den, corr, e0 + e1);
#pragma unroll
        for (int k = 0; k < NH2; k++) {
            float tx = fmaf(xvB[k].x, e1, xvA[k].x * e0);
            float ty = fmaf(xvB[k].y, e1, xvA[k].y * e0);
            acc[k].x = fmaf(acc[k].x, corr, tx);
            acc[k].y = fmaf(acc[k].y, corr, ty);
        }
    }
    if (j < s1) {  // tail edge
        int s = g_csrc[j];
        const __half* ys = y + (size_t)s * (2 * CH) + c0;
        uint32_t vr[NH2];
        if (NH2 == 4) {
            uint4 u = *(const uint4*)ys;
            vr[0] = u.x; vr[1] = u.y; vr[2] = u.z; vr[3] = u.w;
        } else {
            uint2 u = *(const uint2*)ys;
            vr[0] = u.x; vr[1] = u.y;
        }
        float2 xv[NH2];
        float d = 0.f;
#pragma unroll
        for (int k = 0; k < NH2; k++) {
            float2 v = __half22float2(*reinterpret_cast<__half2*>(&vr[k]));
            xv[k] = v;
            float mx = v.x + xr[k].x;
            float my = v.y + xr[k].y;
            mx = fmaxf(mx, 0.2f * mx);
            my = fmaxf(my, 0.2f * my);
            d = fmaf(mx, attv[k].x, d);
            d = fmaf(my, attv[k].y, d);
        }
#pragma unroll
        for (int o = LPH >> 1; o; o >>= 1) d += __shfl_xor_sync(0xffffffffu, d, o);
        float nm = fmaxf(emax, d);
        float corr = __expf(emax - nm);
        float ex = __expf(d - nm);
        emax = nm;
        den = fmaf(den, corr, ex);
#pragma unroll
        for (int k = 0; k < NH2; k++) {
            acc[k].x = fmaf(acc[k].x, corr, ex * xv[k].x);
            acc[k].y = fmaf(acc[k].y, corr, ex * xv[k].y);
        }
    }

    const float inv = 1.f / (den + 1e-16f);
    if (FINAL) {
        if (active) {
            float p0 = 0.f, p1 = 0.f;
#pragma unroll
            for (int k = 0; k < NH2; k++) {
                int ca = c0 + 2 * k, cb = ca + 1;
                float vx = acc[k].x * inv + bias[ca];
                float vy = acc[k].y * inv + bias[cb];
                p0 = fmaf(vx, Wlin[2 * ca + 0], p0);
                p0 = fmaf(vy, Wlin[2 * cb + 0], p0);
                p1 = fmaf(vx, Wlin[2 * ca + 1], p1);
                p1 = fmaf(vy, Wlin[2 * cb + 1], p1);
            }
#pragma unroll
            for (int o = 16; o; o >>= 1) {
                p0 += __shfl_xor_sync(0xffffffffu, p0, o);
                p1 += __shfl_xor_sync(0xffffffffu, p1, o);
            }
            if (lane == 0) {
                int g = batch[t];
                atomicAdd(&g_acc[2 * g + 0], p0);
                atomicAdd(&g_acc[2 * g + 1], p1);
                atomicAdd(&g_cnt[g], 1.f);
            }
        }
        // last-block-done: write the final [GG,2] output (grid has no early exits:
        // 6250 blocks x 8 warps == 50000 nodes exactly)
        __threadfence();
        __syncthreads();
        if (threadIdx.x == 0)
            sLast = (atomicAdd(&g_done, 1u) == gridDim.x - 1) ? 1 : 0;
        __syncthreads();
        if (sLast) {
            for (int g = threadIdx.x; g < GG; g += blockDim.x) {
                float gi = 1.f / fmaxf(g_cnt[g], 1.f);
                out[2 * g + 0] = g_acc[2 * g + 0] * gi + blin[0];
                out[2 * g + 1] = g_acc[2 * g + 1] * gi + blin[1];
            }
        }
    } else {
        if (active) {
            uint32_t o[NH2];
#pragma unroll
            for (int k = 0; k < NH2; k++) {
                float vx = acc[k].x * inv + bias[c0 + 2 * k];
                float vy = acc[k].y * inv + bias[c0 + 2 * k + 1];
                vx = (vx > 0.f) ? vx : expm1f(vx);  // ELU
                vy = (vy > 0.f) ? vy : expm1f(vy);
                o[k] = pkh2(vx, vy);
            }
            __half* hp = hout + (size_t)t * CH + c0;
            if (NH2 == 4) *(uint4*)hp = make_uint4(o[0], o[1], o[2], o[3]);
            else          *(uint2*)hp = make_uint2(o[0], o[1]);
        }
    }
}

// ---------------- BatchNorm stats (fp16 input, fp32 partials + atomics) ----------------
__global__ void k_bnstats(const __half* __restrict__ h) {
    int c = threadIdx.x;  // 256
    float s = 0.f, q = 0.f;
    for (int r = blockIdx.x; r < NN; r += gridDim.x) {
        float v = __half2float(h[(size_t)r * 256 + c]);
        s += v;
        q = fmaf(v, v, q);
    }
    atomicAdd(&g_bnsumF[c], s);
    atomicAdd(&g_bnsqF[c], q);
}

// ---------------- launcher ----------------
extern "C" void kernel_launch(void* const* d_in, const int* in_sizes, int n_in,
                              void* d_out, int out_size) {
    const float* x     = (const float*)d_in[0];
    const int*   ei    = (const int*)d_in[1];
    const int*   batch = (const int*)d_in[2];
    const float* Wl1   = (const float*)d_in[3];
    const float* Wr1   = (const float*)d_in[4];
    const float* att1  = (const float*)d_in[5];
    const float* b1    = (const float*)d_in[6];
    const float* gamma = (const float*)d_in[7];
    const float* beta  = (const float*)d_in[8];
    const float* Wl2   = (const float*)d_in[9];
    const float* Wr2   = (const float*)d_in[10];
    const float* att2  = (const float*)d_in[11];
    const float* b2    = (const float*)d_in[12];
    const float* Wlin  = (const float*)d_in[13];
    const float* blin  = (const float*)d_in[14];
    float* out = (float*)d_out;

    void *p_y1, *p_h1, *p_y2, *p_b1, *p_b2;
    cudaGetSymbolAddress(&p_y1, g_y1);
    cudaGetSymbolAddress(&p_h1, g_h1);
    cudaGetSymbolAddress(&p_y2, g_y2);
    cudaGetSymbolAddress(&p_b1, g_B1);
    cudaGetSymbolAddress(&p_b2, g_B2);
    __half* y1 = (__half*)p_y1;
    __half* h1 = (__half*)p_h1;
    __half* y2 = (__half*)p_y2;

    const int SMEMSZ = 40960 + 2048;  // 2 pipeline stages + BN scale/shift
    static bool s_init = false;
    static cudaStream_t s1;
    static cudaEvent_t evFork, evJoin;
    if (!s_init) {
        cudaFuncSetAttribute(k_mma<128, false, float>, cudaFuncAttributeMaxDynamicSharedMemorySize, SMEMSZ);
        cudaFuncSetAttribute(k_mma<256, true, __half>, cudaFuncAttributeMaxDynamicSharedMemorySize, SMEMSZ);
        cudaStreamCreateWithFlags(&s1, cudaStreamNonBlocking);
        cudaEventCreateWithFlags(&evFork, cudaEventDisableTiming);
        cudaEventCreateWithFlags(&evJoin, cudaEventDisableTiming);
        s_init = true;
    }

    const int MB = (NN + 127) / 128;  // 391

    // ---- fork: side stream does init + B2 convert + CSR build ----
    cudaEventRecord(evFork, 0);
    cudaStreamWaitEvent(s1, evFork, 0);

    // submission order puts mma1 at index 3 (ncu captures submission idx 3)
    k_initMain<<<256, 256, 0, s1>>>();                    // 0 (side)
    k_cvtB2<<<256, 256, 0, s1>>>(Wl2, Wr2);               // 1 (side)
    k_cvtB1<<<256, 256>>>(Wl1, Wr1);                      // 2 (main)
    k_mma<128, false, float><<<dim3(4, MB), 256, SMEMSZ>>>(
        x, (const __half*)p_b1, y1, 512, NN, nullptr, nullptr);  // 3 (main) <- profiled

    // side stream: CSR build
    k_hist<<<(ET + 255) / 256, 256, 0, s1>>>(ei);
    k_scanA<<<SCB, 1024, 0, s1>>>();
    k_scanC<<<SCB, 1024, 0, s1>>>();
    k_fill<<<(ET + 255) / 256, 256, 0, s1>>>(ei);
    cudaEventRecord(evJoin, s1);
    cudaStreamWaitEvent(0, evJoin, 0);

    // ---- joined: agg1 -> BN stats -> layer2 (bnfin folded into mma2) ----
    k_agg<2, false><<<(NN * 32 + 255) / 256, 256>>>(y1, att1, b1, h1, nullptr, nullptr, nullptr, nullptr);
    k_bnstats<<<512, 256>>>(h1);

    k_mma<256, true, __half><<<dim3(2, MB), 256, SMEMSZ>>>(
        h1, (const __half*)p_b2, y2, 256, NN, gamma, beta);
    // agg2 with fused projection + final output (last-block-done)
    k_agg<1, true><<<(NN * 32 + 255) / 256, 256>>>(y2, att2, b2, nullptr, batch, Wlin, blin, out);
}

// round 17
// speedup vs baseline: 1.3676x; 1.3676x over previous
#include <cuda_runtime.h>
#include <cuda_fp16.h>
#include <math.h>
#include <stdint.h>

#define NN 50000
#define EE 800000
#define ET 850000   // EE + NN self loops
#define GG 512
#define SCB 25      // scan blocks (2048 elems each)

// ---------------- static scratch (no allocations allowed) ----------------
__device__ __align__(128) __half g_y1[(size_t)NN * 512];  // [xl1 | xr1] fp16
__device__ __align__(128) __half g_h1[(size_t)NN * 256];  // post-ELU layer1 output fp16
__device__ __align__(128) __half g_y2[(size_t)NN * 256];  // [xl2 | xr2] fp16
__device__ __align__(128) __half g_B1[512 * 128];  // layer1 B^T fp16 [n][k]
__device__ __align__(128) __half g_B2[256 * 256];  // layer2 B^T fp16 [n][k]
__device__ int    g_deg[NN];
__device__ int    g_off[NN + 1];
__device__ int    g_cur[NN];
__device__ int    g_csrc[ET];
__device__ int    g_blksum[32];
__device__ float  g_bnsumF[256];
__device__ float  g_bnsqF[256];
__device__ float  g_acc[GG * 2];   // per-graph projected sums
__device__ float  g_cnt[GG];

// ---------------- PTX helpers (baseline sm_80/sm_90 features only) ----------------
__device__ __forceinline__ uint32_t smem_u32(const void* p) {
    uint32_t r;
    asm("{ .reg .u64 t; cvta.to.shared.u64 t, %1; cvt.u32.u64 %0, t; }" : "=r"(r) : "l"(p));
    return r;
}
#define CP_ASYNC16(dst, src) \
    asm volatile("cp.async.cg.shared.global [%0], [%1], 16;" :: "r"(dst), "l"(src) : "memory")
#define CP_COMMIT() asm volatile("cp.async.commit_group;" ::: "memory")
#define CP_WAIT(n)  asm volatile("cp.async.wait_group %0;" :: "n"(n) : "memory")
#define LDM_X4(r0, r1, r2, r3, addr) \
    asm volatile("ldmatrix.sync.aligned.m8n8.x4.shared.b16 {%0,%1,%2,%3}, [%4];" \
        : "=r"(r0), "=r"(r1), "=r"(r2), "=r"(r3) : "r"(addr))
#define MMA_F16(cc, a, b0v, b1v) \
    asm volatile("mma.sync.aligned.m16n8k16.row.col.f32.f16.f16.f32 " \
        "{%0,%1,%2,%3}, {%4,%5,%6,%7}, {%8,%9}, {%0,%1,%2,%3};" \
        : "+f"((cc)[0]), "+f"((cc)[1]), "+f"((cc)[2]), "+f"((cc)[3]) \
        : "r"((a)[0]), "r"((a)[1]), "r"((a)[2]), "r"((a)[3]), "r"(b0v), "r"(b1v))

__device__ __forceinline__ uint32_t pkh2(float a, float b) {
    __half2 t = __floats2half2_rn(a, b);
    return *reinterpret_cast<uint32_t*>(&t);
}

// ---------------- init (on CSR side stream; zeroes deg for hist) ----------------
__global__ void k_initMain() {
    int i = blockIdx.x * blockDim.x + threadIdx.x;  // 65536 threads
    if (i < GG * 2) g_acc[i] = 0.f;
    if (i < GG) g_cnt[i] = 0.f;
    if (i < 256) { g_bnsumF[i] = 0.f; g_bnsqF[i] = 0.f; }
    if (i < NN) g_deg[i] = 0;
}

// ---------------- convert & transpose weights (fp16) ----------------
__global__ void k_cvtB1(const float* __restrict__ Wl1, const float* __restrict__ Wr1) {
    int i = blockIdx.x * blockDim.x + threadIdx.x;  // 65536 threads
    if (i < 512 * 128) {
        int n = i >> 7, k = i & 127;
        float w = (n < 256) ? Wl1[k * 256 + n] : Wr1[k * 256 + (n - 256)];
        g_B1[i] = __float2half(w);
    }
}

__global__ void k_cvtB2(const float* __restrict__ Wl2, const float* __restrict__ Wr2) {
    int j = blockIdx.x * blockDim.x + threadIdx.x;  // 65536 threads
    if (j < 256 * 256) {
        int n = j >> 8, k = j & 255;
        float w = (n < 128) ? Wl2[k * 128 + n] : Wr2[k * 128 + (n - 128)];
        g_B2[j] = __float2half(w);
    }
}

// ---------------- CSR build ----------------
__global__ void k_hist(const int* __restrict__ ei) {
    int i = blockIdx.x * blockDim.x + threadIdx.x;
    if (i >= ET) return;
    int dst = (i < EE) ? ei[EE + i] : (i - EE);
    atomicAdd(&g_deg[dst], 1);
}

// hierarchical scan: A) block sums, C) per-block scan of sums + full scan + write
__global__ void k_scanA() {  // grid SCB, block 1024
    __shared__ int ws[32];
    const int b = blockIdx.x, t = threadIdx.x;
    const int i = b * 2048 + 2 * t;
    int v0 = 0, v1 = 0;
    if (i + 1 < NN) { int2 p = *(const int2*)&g_deg[i]; v0 = p.x; v1 = p.y; }
    else if (i < NN) v0 = g_deg[i];
    int s = v0 + v1;
#pragma unroll
    for (int o = 16; o; o >>= 1) s += __shfl_xor_sync(0xffffffffu, s, o);
    if ((t & 31) == 0) ws[t >> 5] = s;
    __syncthreads();
    if (t < 32) {
        int x = ws[t];
#pragma unroll
        for (int o = 16; o; o >>= 1) x += __shfl_xor_sync(0xffffffffu, x, o);
        if (t == 0) g_blksum[b] = x;
    }
}

__global__ void k_scanC() {  // grid SCB, block 1024: scans blksums itself, then full scan
    __shared__ int ws[32];
    __shared__ int sOff, sTotal;
    const int b = blockIdx.x, t = threadIdx.x;
    const int lane = t & 31, w = t >> 5;

    if (t < 32) {  // warp 0: exclusive-scan the 25 block sums
        int v = (t < SCB) ? g_blksum[t] : 0;
        int x = v;
#pragma unroll
        for (int o = 1; o < 32; o <<= 1) {
            int u = __shfl_up_sync(0xffffffffu, x, o);
            if (t >= o) x += u;
        }
        if (t == b) sOff = x - v;
        if (t == SCB - 1) sTotal = x;
    }

    const int i = b * 2048 + 2 * t;
    int v0 = 0, v1 = 0;
    if (i + 1 < NN) { int2 p = *(const int2*)&g_deg[i]; v0 = p.x; v1 = p.y; }
    else if (i < NN) v0 = g_deg[i];
    int s = v0 + v1;
    int x = s;
#pragma unroll
    for (int o = 1; o < 32; o <<= 1) {
        int u = __shfl_up_sync(0xffffffffu, x, o);
        if (lane >= o) x += u;
    }
    if (lane == 31) ws[w] = x;
    __syncthreads();
    if (w == 0) {
        int y = ws[lane];
#pragma unroll
        for (int o = 1; o < 32; o <<= 1) {
            int u = __shfl_up_sync(0xffffffffu, y, o);
            if (lane >= o) y += u;
        }
        ws[lane] = y;
    }
    __syncthreads();
    int excl = x - s + (w > 0 ? ws[w - 1] : 0) + sOff;
    if (i < NN) { g_off[i] = excl; g_cur[i] = excl; }
    if (i + 1 < NN) { g_off[i + 1] = excl + v0; g_cur[i + 1] = excl + v0; }
    if (b == SCB - 1 && t == 1023) g_off[NN] = sTotal;
}

__global__ void k_fill(const int* __restrict__ ei) {
    int i = blockIdx.x * blockDim.x + threadIdx.x;
    if (i >= ET) return;
    int src = (i < EE) ? ei[i] : (i - EE);
    int dst = (i < EE) ? ei[EE + i] : (i - EE);
    int p = atomicAdd(&g_cur[dst], 1);
    g_csrc[p] = src;
}

// ---------------- single-pass fp16 mma.sync GEMM ----------------
// NORM: compute BN scale/shift per block from raw sums (folds bnfin).
template <int K, bool NORM, typename TA>
__global__ void __launch_bounds__(256, 2) k_mma(
    const TA* __restrict__ A,
    const __half* __restrict__ B,
    __half* __restrict__ C, int ldc, int M,
    const float* __restrict__ gamma, const float* __restrict__ beta) {
    extern __shared__ __align__(128) char smem[];
    constexpr int NC = K / 32;
    const int tid = threadIdx.x, lane = tid & 31, wid = tid >> 5;
    const int row0 = blockIdx.y * 128, n0 = blockIdx.x * 128;
    const int wm = (wid & 3) * 32, wn = (wid >> 2) * 64;
    const uint32_t sb = smem_u32(smem);
    float* sScale = (float*)(smem + 40960);
    float* sShift = (float*)(smem + 40960 + 1024);

    if (NORM) {
        if (tid < K) {
            float mu = g_bnsumF[tid] * (1.f / (float)NN);
            float var = g_bnsqF[tid] * (1.f / (float)NN) - mu * mu;
            float sc = gamma[tid] * rsqrtf(var + 1e-5f);
            sScale[tid] = sc;
            sShift[tid] = beta[tid] - mu * sc;
        }
        __syncthreads();
    }

    float c[2][8][4];
#pragma unroll
    for (int mf = 0; mf < 2; mf++)
#pragma unroll
        for (int nf = 0; nf < 8; nf++)
#pragma unroll
            for (int q = 0; q < 4; q++) c[mf][nf][q] = 0.f;

    const int ar = tid >> 1;             // A row within tile
    const int ac = (tid & 1) * 16;       // A col-seg within chunk
    const int agr = min(row0 + ar, M - 1);

    auto ldgA = [&](int ch, float* f) {
        const TA* ap = A + (size_t)agr * K + ch * 32 + ac;
        if (sizeof(TA) == 4) {
            const float* fp = (const float*)ap;
#pragma unroll
            for (int q = 0; q < 4; q++) {
                float4 v = *(const float4*)(fp + q * 4);
                f[q * 4 + 0] = v.x; f[q * 4 + 1] = v.y;
                f[q * 4 + 2] = v.z; f[q * 4 + 3] = v.w;
            }
        } else {
            const __half2* hp = (const __half2*)ap;
#pragma unroll
            for (int q = 0; q < 8; q++) {
                float2 v = __half22float2(hp[q]);
                f[q * 2 + 0] = v.x; f[q * 2 + 1] = v.y;
            }
        }
    };
    auto stsA = [&](int ch, float* f) {
        const uint32_t base = (uint32_t)(ch & 1) * 20480u;
        if (NORM) {
            const int c0 = ch * 32 + ac;
#pragma unroll
            for (int i = 0; i < 16; i++) f[i] = fmaf(f[i], sScale[c0 + i], sShift[c0 + i]);
        }
        uint4 H0 = make_uint4(pkh2(f[0], f[1]), pkh2(f[2], f[3]), pkh2(f[4], f[5]), pkh2(f[6], f[7]));
        uint4 H1 = make_uint4(pkh2(f[8], f[9]), pkh2(f[10], f[11]), pkh2(f[12], f[13]), pkh2(f[14], f[15]));
        const uint32_t off = base + (uint32_t)ar * 80u + (uint32_t)ac * 2u;
        *(uint4*)(smem + off) = H0;
        *(uint4*)(smem + off + 16) = H1;
    };
    auto issueB = [&](int ch) {
        const int k0 = ch * 32;
        const uint32_t base = sb + (uint32_t)(ch & 1) * 20480u + 10240u;
#pragma unroll
        for (int j = 0; j < 2; j++) {
            int seg = tid + 256 * j;
            int r = seg >> 2, s = seg & 3;
            const void* src = B + (size_t)(n0 + r) * K + k0 + s * 8;
            uint32_t dst = base + (uint32_t)r * 80u + (uint32_t)s * 16u;
            CP_ASYNC16(dst, src);
        }
    };

    // prologue
    float areg[16];
    ldgA(0, areg);
    stsA(0, areg);
    issueB(0);
    CP_COMMIT();
    if (NC > 1) {
        issueB(1);
        CP_COMMIT();
        ldgA(1, areg);
    }

    // ldmatrix per-lane address pieces
    const int grp = lane >> 3, r8 = lane & 7;
    const uint32_t a_row = (uint32_t)(((grp & 1) ? 8 : 0) + r8);
    const uint32_t a_k16 = (grp & 2) ? 16u : 0u;
    const uint32_t b_row = (uint32_t)(((grp & 2) ? 8 : 0) + r8);
    const uint32_t b_k16 = (grp & 1) ? 16u : 0u;

    for (int ch = 0; ch < NC; ch++) {
        if (ch + 1 < NC) { CP_WAIT(1); } else { CP_WAIT(0); }
        __syncthreads();
        const uint32_t sA = sb + (uint32_t)(ch & 1) * 20480u;
#pragma unroll
        for (int ks = 0; ks < 2; ks++) {
            const uint32_t ko = (uint32_t)ks * 32u;
            uint32_t ah[2][4], bh[4][4];
#pragma unroll
            for (int mf = 0; mf < 2; mf++) {
                uint32_t addr = sA + ((uint32_t)(wm + mf * 16) + a_row) * 80u + ko + a_k16;
                LDM_X4(ah[mf][0], ah[mf][1], ah[mf][2], ah[mf][3], addr);
            }
#pragma unroll
            for (int pf = 0; pf < 4; pf++) {
                uint32_t addr = sA + 10240u + ((uint32_t)(wn + pf * 16) + b_row) * 80u + ko + b_k16;
                LDM_X4(bh[pf][0], bh[pf][1], bh[pf][2], bh[pf][3], addr);
            }
#pragma unroll
            for (int mf = 0; mf < 2; mf++)
#pragma unroll
                for (int nf = 0; nf < 8; nf++) {
                    const int pf = nf >> 1, h = (nf & 1) * 2;
                    MMA_F16(c[mf][nf], ah[mf], bh[pf][h], bh[pf][h + 1]);
                }
        }
        if (ch + 1 < NC) {
            stsA(ch + 1, areg);               // other buffer: safe pre-sync
            if (ch + 2 < NC) ldgA(ch + 2, areg);
        }
        __syncthreads();
        if (ch + 2 < NC) {
            issueB(ch + 2);                    // reuses buffer (ch&1): safe post-sync
            CP_COMMIT();
        }
    }

    // epilogue (fp16 stores)
    const int g = lane >> 2, tg = lane & 3;
#pragma unroll
    for (int mf = 0; mf < 2; mf++) {
        int row = row0 + wm + mf * 16 + g;
#pragma unroll
        for (int nf = 0; nf < 8; nf++) {
            int col = n0 + wn + nf * 8 + 2 * tg;
            if (row < M)
                *(__half2*)(C + (size_t)row * ldc + col) = __floats2half2_rn(c[mf][nf][0], c[mf][nf][1]);
            if (row + 8 < M)
                *(__half2*)(C + (size_t)(row + 8) * ldc + col) = __floats2half2_rn(c[mf][nf][2], c[mf][nf][3]);
        }
    }
}

// ---------------- GATv2 aggregation: warp per dst node, branch-free online softmax ----
// Lane owns a contiguous block of NCH channels (one vector load per edge).
// FINAL: fuse mean-pool projection (@Wlin) -> 2 atomics per node.
template <int HEADS, bool FINAL>
__global__ void k_agg(const __half* __restrict__ y,     // [NN, 2*CH] = [xl | xr] fp16
                      const float* __restrict__ att,    // [CH]
                      const float* __restrict__ bias,   // [CH]
                      __half* __restrict__ hout,        // [NN, CH] fp16 (if !FINAL)
                      const int* __restrict__ batch,
                      const float* __restrict__ Wlin) { // [CH, 2] (if FINAL)
    constexpr int CH = HEADS * 128;
    constexpr int NCH = CH / 32;       // channels per lane (8 or 4)
    constexpr int NH2 = NCH / 2;       // half2 per lane (4 or 2)
    constexpr int LPH = 32 / HEADS;    // lanes per head
    const int lane = threadIdx.x & 31;
    const int t = (blockIdx.x * blockDim.x + threadIdx.x) >> 5;
    if (t >= NN) return;
    const int c0 = NCH * lane;         // this lane's first channel

    const __half* yt = y + (size_t)t * (2 * CH) + CH + c0;  // xr[t] block
    float2 xr[NH2], attv[NH2], acc[NH2];
#pragma unroll
    for (int k = 0; k < NH2; k++) {
        xr[k] = __half22float2(*(const __half2*)(yt + 2 * k));
        attv[k] = make_float2(att[c0 + 2 * k], att[c0 + 2 * k + 1]);
        acc[k] = make_float2(0.f, 0.f);
    }
    float emax = -1e30f, den = 0.f;

    const int s0 = g_off[t], s1 = g_off[t + 1];
#pragma unroll 2
    for (int j = s0; j < s1; j++) {
        int s = g_csrc[j];
        const __half* ys = y + (size_t)s * (2 * CH) + c0;  // xl[s] block
        uint32_t vr[NH2];
        if (NH2 == 4) {
            uint4 u = *(const uint4*)ys;
            vr[0] = u.x; vr[1] = u.y; vr[2] = u.z; vr[3] = u.w;
        } else {
            uint2 u = *(const uint2*)ys;
            vr[0] = u.x; vr[1] = u.y;
        }
        float2 xv[NH2];
        float d = 0.f;
#pragma unroll
        for (int k = 0; k < NH2; k++) {
            float2 v = __half22float2(*reinterpret_cast<__half2*>(&vr[k]));
            xv[k] = v;
            float mx = v.x + xr[k].x;
            float my = v.y + xr[k].y;
            mx = fmaxf(mx, 0.2f * mx);   // leaky relu
            my = fmaxf(my, 0.2f * my);
            d = fmaf(mx, attv[k].x, d);
            d = fmaf(my, attv[k].y, d);
        }
#pragma unroll
        for (int o = LPH >> 1; o; o >>= 1) d += __shfl_xor_sync(0xffffffffu, d, o);

        float nm = fmaxf(emax, d);
        float corr = __expf(emax - nm);
        float ex = __expf(d - nm);
        emax = nm;
        den = fmaf(den, corr, ex);
#pragma unroll
        for (int k = 0; k < NH2; k++) {
            acc[k].x = fmaf(acc[k].x, corr, ex * xv[k].x);
            acc[k].y = fmaf(acc[k].y, corr, ex * xv[k].y);
        }
    }

    const float inv = 1.f / (den + 1e-16f);
    if (FINAL) {
        // per-node projection: p = h[t] @ Wlin  (2 scalars), then per-graph sum
        float p0 = 0.f, p1 = 0.f;
#pragma unroll
        for (int k = 0; k < NH2; k++) {
            int ca = c0 + 2 * k, cb = ca + 1;
            float vx = acc[k].x * inv + bias[ca];
            float vy = acc[k].y * inv + bias[cb];
            p0 = fmaf(vx, Wlin[2 * ca + 0], p0);
            p0 = fmaf(vy, Wlin[2 * cb + 0], p0);
            p1 = fmaf(vx, Wlin[2 * ca + 1], p1);
            p1 = fmaf(vy, Wlin[2 * cb + 1], p1);
        }
#pragma unroll
        for (int o = 16; o; o >>= 1) {
            p0 += __shfl_xor_sync(0xffffffffu, p0, o);
            p1 += __shfl_xor_sync(0xffffffffu, p1, o);
        }
        if (lane == 0) {
            int g = batch[t];
            atomicAdd(&g_acc[2 * g + 0], p0);
            atomicAdd(&g_acc[2 * g + 1], p1);
            atomicAdd(&g_cnt[g], 1.f);
        }
    } else {
        uint32_t o[NH2];
#pragma unroll
        for (int k = 0; k < NH2; k++) {
            float vx = acc[k].x * inv + bias[c0 + 2 * k];
            float vy = acc[k].y * inv + bias[c0 + 2 * k + 1];
            vx = (vx > 0.f) ? vx : expm1f(vx);  // ELU
            vy = (vy > 0.f) ? vy : expm1f(vy);
            o[k] = pkh2(vx, vy);
        }
        __half* hp = hout + (size_t)t * CH + c0;
        if (NH2 == 4) *(uint4*)hp = make_uint4(o[0], o[1], o[2], o[3]);
        else          *(uint2*)hp = make_uint2(o[0], o[1]);
    }
}

// ---------------- BatchNorm stats (half2 loads, fp32 partials + atomics) ----------------
__global__ void k_bnstats(const __half* __restrict__ h) {
    const int p = threadIdx.x & 127;       // channel pair index (channels 2p, 2p+1)
    const int rp = threadIdx.x >> 7;       // row phase 0/1
    float2 s = make_float2(0.f, 0.f), q = make_float2(0.f, 0.f);
    for (int r = blockIdx.x * 2 + rp; r < NN; r += gridDim.x * 2) {
        float2 v = __half22float2(*(const __half2*)(h + (size_t)r * 256 + 2 * p));
        s.x += v.x; s.y += v.y;
        q.x = fmaf(v.x, v.x, q.x);
        q.y = fmaf(v.y, v.y, q.y);
    }
    atomicAdd(&g_bnsumF[2 * p + 0], s.x);
    atomicAdd(&g_bnsumF[2 * p + 1], s.y);
    atomicAdd(&g_bnsqF[2 * p + 0], q.x);
    atomicAdd(&g_bnsqF[2 * p + 1], q.y);
}

// ---------------- final: scale per-graph sums + bias ----------------
__global__ void k_final(const float* __restrict__ blin, float* __restrict__ out) {
    int g = blockIdx.x * blockDim.x + threadIdx.x;
    if (g < GG) {
        float inv = 1.f / fmaxf(g_cnt[g], 1.f);
        out[2 * g + 0] = g_acc[2 * g + 0] * inv + blin[0];
        out[2 * g + 1] = g_acc[2 * g + 1] * inv + blin[1];
    }
}

// ---------------- launcher ----------------
extern "C" void kernel_launch(void* const* d_in, const int* in_sizes, int n_in,
                              void* d_out, int out_size) {
    const float* x     = (const float*)d_in[0];
    const int*   ei    = (const int*)d_in[1];
    const int*   batch = (const int*)d_in[2];
    const float* Wl1   = (const float*)d_in[3];
    const float* Wr1   = (const float*)d_in[4];
    const float* att1  = (const float*)d_in[5];
    const float* b1    = (const float*)d_in[6];
    const float* gamma = (const float*)d_in[7];
    const float* beta  = (const float*)d_in[8];
    const float* Wl2   = (const float*)d_in[9];
    const float* Wr2   = (const float*)d_in[10];
    const float* att2  = (const float*)d_in[11];
    const float* b2    = (const float*)d_in[12];
    const float* Wlin  = (const float*)d_in[13];
    const float* blin  = (const float*)d_in[14];
    float* out = (float*)d_out;

    void *p_y1, *p_h1, *p_y2, *p_b1, *p_b2;
    cudaGetSymbolAddress(&p_y1, g_y1);
    cudaGetSymbolAddress(&p_h1, g_h1);
    cudaGetSymbolAddress(&p_y2, g_y2);
    cudaGetSymbolAddress(&p_b1, g_B1);
    cudaGetSymbolAddress(&p_b2, g_B2);
    __half* y1 = (__half*)p_y1;
    __half* h1 = (__half*)p_h1;
    __half* y2 = (__half*)p_y2;

    const int SMEMSZ = 40960 + 2048;  // 2 pipeline stages + BN scale/shift
    static bool s_init = false;
    static cudaStream_t s1;
    static cudaEvent_t evFork, evJoin;
    if (!s_init) {
        cudaFuncSetAttribute(k_mma<128, false, float>, cudaFuncAttributeMaxDynamicSharedMemorySize, SMEMSZ);
        cudaFuncSetAttribute(k_mma<256, true, __half>, cudaFuncAttributeMaxDynamicSharedMemorySize, SMEMSZ);
        cudaStreamCreateWithFlags(&s1, cudaStreamNonBlocking);
        cudaEventCreateWithFlags(&evFork, cudaEventDisableTiming);
        cudaEventCreateWithFlags(&evJoin, cudaEventDisableTiming);
        s_init = true;
    }

    const int MB = (NN + 127) / 128;  // 391

    // ---- fork: side stream does init + B2 convert + CSR build ----
    cudaEventRecord(evFork, 0);
    cudaStreamWaitEvent(s1, evFork, 0);

    // submission order keeps mma1 at index 3 (ncu captures submission idx 3)
    k_initMain<<<256, 256, 0, s1>>>();                    // 0 (side)
    k_cvtB2<<<256, 256, 0, s1>>>(Wl2, Wr2);               // 1 (side)
    k_cvtB1<<<256, 256>>>(Wl1, Wr1);                      // 2 (main)
    k_mma<128, false, float><<<dim3(4, MB), 256, SMEMSZ>>>(
        x, (const __half*)p_b1, y1, 512, NN, nullptr, nullptr);  // 3 (main) <- profiled

    // side stream: CSR build
    k_hist<<<(ET + 255) / 256, 256, 0, s1>>>(ei);
    k_scanA<<<SCB, 1024, 0, s1>>>();
    k_scanC<<<SCB, 1024, 0, s1>>>();
    k_fill<<<(ET + 255) / 256, 256, 0, s1>>>(ei);
    cudaEventRecord(evJoin, s1);
    cudaStreamWaitEvent(0, evJoin, 0);

    // ---- joined: agg1 -> BN stats -> layer2 (bnfin folded into mma2) ----
    k_agg<2, false><<<(NN * 32 + 255) / 256, 256>>>(y1, att1, b1, h1, nullptr, nullptr);
    k_bnstats<<<512, 256>>>(h1);

    k_mma<256, true, __half><<<dim3(2, MB), 256, SMEMSZ>>>(
        h1, (const __half*)p_b2, y2, 256, NN, gamma, beta);
    k_agg<1, true><<<(NN * 32 + 255) / 256, 256>>>(y2, att2, b2, nullptr, batch, Wlin);

    // final: per-graph mean + bias
    k_final<<<2, 256>>>(blin, out);
}